// round 1
// baseline (speedup 1.0000x reference)
#include <cuda_runtime.h>
#include <cstdint>

// MultiScaleDeformableAttention
// value:              (8, 22223, 8, 32)  float32
// sampling_locations: (8, 900, 8, 4, 4, 2) float32
// attention_weights:  (8, 900, 8, 4, 4) float32
// out:                (8, 900, 256) float32  == (b, q, h*32+c)
//
// One warp per (b,q,h). lane = channel c in [0,32). Each bilinear tap is a
// coalesced 128B load of value[b, key, h, :]. loc/weight loads are
// warp-uniform (broadcast).

#define BS  8
#define NQ  900
#define NH  8
#define DC  32
#define NL  4
#define NPT 4

__constant__ int c_dummy; // (unused)

__global__ __launch_bounds__(256) void msda_kernel(
    const float* __restrict__ value,
    const float* __restrict__ loc,
    const float* __restrict__ aw,
    float* __restrict__ out)
{
    // level geometry (compile-time)
    const int Hs[NL]     = {100, 50, 25, 13};
    const int Ws[NL]     = {167, 84, 42, 21};
    const int starts[NL] = {0, 16700, 20900, 21950}; // prefix sums of H*W
    // NUM_KEYS = 22223

    const int gtid = blockIdx.x * blockDim.x + threadIdx.x;
    const int warp = gtid >> 5;          // (b*NQ+q)*NH + h
    const int lane = gtid & 31;          // channel
    const int NWARPS = BS * NQ * NH;
    if (warp >= NWARPS) return;

    const int h  = warp & (NH - 1);
    const int bq = warp >> 3;            // b*NQ + q
    const int b  = bq / NQ;

    // base offset into value for (b, h, lane): add key*NH*DC per tap
    const int vbase = ((b * 22223) * NH + h) * DC + lane;

    float acc = 0.0f;

    #pragma unroll
    for (int lvl = 0; lvl < NL; ++lvl) {
        const int H = Hs[lvl];
        const int W = Ws[lvl];
        const int start = starts[lvl];

        #pragma unroll
        for (int pt = 0; pt < NPT; ++pt) {
            const int li = ((warp * NL + lvl) * NPT + pt);
            const float lx = __ldg(loc + 2 * li);
            const float ly = __ldg(loc + 2 * li + 1);
            const float w  = __ldg(aw + li);

            const float x = lx * (float)W - 0.5f;
            const float y = ly * (float)H - 0.5f;
            const float xf = floorf(x);
            const float yf = floorf(y);
            const int x0 = (int)xf;
            const int y0 = (int)yf;
            const int x1 = x0 + 1;
            const int y1 = y0 + 1;
            const float wx1 = x - xf;
            const float wx0 = 1.0f - wx1;
            const float wy1 = y - yf;
            const float wy0 = 1.0f - wy1;

            const bool vx0 = (x0 >= 0) & (x0 < W);
            const bool vx1 = (x1 >= 0) & (x1 < W);
            const bool vy0 = (y0 >= 0) & (y0 < H);
            const bool vy1 = (y1 >= 0) & (y1 < H);

            // issue the (up to) 4 independent loads first for MLP
            float v00 = 0.0f, v10 = 0.0f, v01 = 0.0f, v11 = 0.0f;
            if (vx0 & vy0) v00 = __ldg(value + vbase + (start + y0 * W + x0) * (NH * DC));
            if (vx1 & vy0) v10 = __ldg(value + vbase + (start + y0 * W + x1) * (NH * DC));
            if (vx0 & vy1) v01 = __ldg(value + vbase + (start + y1 * W + x0) * (NH * DC));
            if (vx1 & vy1) v11 = __ldg(value + vbase + (start + y1 * W + x1) * (NH * DC));

            const float bilin = v00 * (wx0 * wy0) + v10 * (wx1 * wy0)
                              + v01 * (wx0 * wy1) + v11 * (wx1 * wy1);
            acc = fmaf(w, bilin, acc);
        }
    }

    // out[(b*NQ+q)*NH*DC + h*DC + lane] == warp*32 + lane
    out[warp * DC + lane] = acc;
}

extern "C" void kernel_launch(void* const* d_in, const int* in_sizes, int n_in,
                              void* d_out, int out_size)
{
    const float* value = (const float*)d_in[0];
    const float* loc   = (const float*)d_in[1];
    const float* aw    = (const float*)d_in[2];
    float* out         = (float*)d_out;

    const int nwarps  = BS * NQ * NH;          // 57600
    const int threads = 256;
    const int blocks  = (nwarps * 32 + threads - 1) / threads;  // 7200
    msda_kernel<<<blocks, threads>>>(value, loc, aw, out);
}

// round 3
// speedup vs baseline: 1.6600x; 1.6600x over previous
#include <cuda_runtime.h>
#include <cstdint>

// MultiScaleDeformableAttention — GB300
// value:              (8, 22223, 8, 32)  float32
// sampling_locations: (8, 900, 8, 4, 4, 2) float32
// attention_weights:  (8, 900, 8, 4, 4) float32
// out:                (8, 900, 256) float32
//
// One warp per (b,q,h).
//   lane = (g, cp): g = lane>>3 selects one of the 4 sampling points of the
//   current level, cp = lane&7 selects a float4 channel quad (32 ch = 8 quads).
// Each level iteration processes all 4 points of that level in parallel
// across the lane-octets; each tap is an LDG.128 (8 lanes x 16B = 128B
// coalesced). Scalar loc/weight math is issued once per level instead of
// once per point -> ~4x fewer ALU instructions than the scalar version.
// Cross-point reduction at the end via 2 rounds of shfl_xor.

#define BS  8
#define NQ  900
#define NH  8
#define DC  32
#define NL  4
#define NPT 4
#define NKEYS 22223
#define KSTRIDE4 (NH * DC / 4)   // float4s per key row = 64

__global__ __launch_bounds__(256) void msda_kernel(
    const float* __restrict__ value,
    const float* __restrict__ loc,
    const float* __restrict__ aw,
    float* __restrict__ out)
{
    const int Hs[NL]     = {100, 50, 25, 13};
    const int Ws[NL]     = {167, 84, 42, 21};
    const int starts[NL] = {0, 16700, 20900, 21950};

    const int gtid = blockIdx.x * blockDim.x + threadIdx.x;
    const int warp = gtid >> 5;          // (b*NQ+q)*NH + h
    const int lane = gtid & 31;
    if (warp >= BS * NQ * NH) return;

    const int g  = lane >> 3;            // point index within level (0..3)
    const int cp = lane & 7;             // channel quad (0..7)

    const int h  = warp & (NH - 1);
    const int bq = warp >> 3;
    const int b  = bq / NQ;

    // float4 view of value for (b, h, quad cp); add key*KSTRIDE4 per tap
    const float4* __restrict__ v4 =
        (const float4*)value + ((size_t)(b * NKEYS) * NH + h) * (DC / 4) + cp;

    const float2* __restrict__ loc2 = (const float2*)loc;

    float4 acc = make_float4(0.f, 0.f, 0.f, 0.f);

    #pragma unroll
    for (int lvl = 0; lvl < NL; ++lvl) {
        const int H = Hs[lvl];
        const int W = Ws[lvl];
        const int start = starts[lvl];

        // this lane's point: index (warp, lvl, g)
        const int li = (warp * NL + lvl) * NPT + g;
        const float2 l2 = __ldg(loc2 + li);
        const float w   = __ldg(aw + li);

        const float x = l2.x * (float)W - 0.5f;
        const float y = l2.y * (float)H - 0.5f;
        const float xf = floorf(x);
        const float yf = floorf(y);
        const int x0 = (int)xf;
        const int y0 = (int)yf;
        const int x1 = x0 + 1;
        const int y1 = y0 + 1;
        const float wx1 = x - xf;
        const float wx0 = 1.0f - wx1;
        const float wy1 = y - yf;
        const float wy0 = 1.0f - wy1;

        // fold attention weight into the 4 tap weights
        const float w00 = w * wx0 * wy0;
        const float w10 = w * wx1 * wy0;
        const float w01 = w * wx0 * wy1;
        const float w11 = w * wx1 * wy1;

        const bool vx0 = (x0 >= 0) & (x0 < W);
        const bool vx1 = (x1 >= 0) & (x1 < W);
        const bool vy0 = (y0 >= 0) & (y0 < H);
        const bool vy1 = (y1 >= 0) & (y1 < H);

        // premultiplied row offsets (in float4 units)
        const long r0 = (long)(start + y0 * W) * KSTRIDE4;
        const long r1 = r0 + (long)W * KSTRIDE4;
        const long dx0 = (long)x0 * KSTRIDE4;
        const long dx1 = dx0 + KSTRIDE4;

        float4 v00 = make_float4(0.f,0.f,0.f,0.f);
        float4 v10 = v00, v01 = v00, v11 = v00;
        if (vx0 & vy0) v00 = __ldg(v4 + r0 + dx0);
        if (vx1 & vy0) v10 = __ldg(v4 + r0 + dx1);
        if (vx0 & vy1) v01 = __ldg(v4 + r1 + dx0);
        if (vx1 & vy1) v11 = __ldg(v4 + r1 + dx1);

        acc.x += v00.x * w00 + v10.x * w10 + v01.x * w01 + v11.x * w11;
        acc.y += v00.y * w00 + v10.y * w10 + v01.y * w01 + v11.y * w11;
        acc.z += v00.z * w00 + v10.z * w10 + v01.z * w01 + v11.z * w11;
        acc.w += v00.w * w00 + v10.w * w10 + v01.w * w01 + v11.w * w11;
    }

    // reduce the 4 point-groups (lanes cp, cp+8, cp+16, cp+24)
    #pragma unroll
    for (int m = 8; m <= 16; m <<= 1) {
        acc.x += __shfl_xor_sync(0xffffffffu, acc.x, m);
        acc.y += __shfl_xor_sync(0xffffffffu, acc.y, m);
        acc.z += __shfl_xor_sync(0xffffffffu, acc.z, m);
        acc.w += __shfl_xor_sync(0xffffffffu, acc.w, m);
    }

    if (g == 0) {
        ((float4*)out)[(size_t)warp * (DC / 4) + cp] = acc;
    }
}

extern "C" void kernel_launch(void* const* d_in, const int* in_sizes, int n_in,
                              void* d_out, int out_size)
{
    const float* value = (const float*)d_in[0];
    const float* loc   = (const float*)d_in[1];
    const float* aw    = (const float*)d_in[2];
    float* out         = (float*)d_out;

    const int nwarps  = BS * NQ * NH;                     // 57600
    const int threads = 256;
    const int blocks  = (nwarps * 32 + threads - 1) / threads;  // 7200
    msda_kernel<<<blocks, threads>>>(value, loc, aw, out);
}

// round 4
// speedup vs baseline: 1.7058x; 1.0276x over previous
#include <cuda_runtime.h>
#include <cstdint>

// MultiScaleDeformableAttention — GB300
// value:              (8, 22223, 8, 32)  float32
// sampling_locations: (8, 900, 8, 4, 4, 2) float32
// attention_weights:  (8, 900, 8, 4, 4) float32
// out:                (8, 900, 256) float32
//
// One warp per (b,q,h). lane = (g, cp): g = lane>>3 picks the point within a
// level, cp = lane&7 picks a float4 channel quad. Two phases:
//   A: compute ALL 16 tap offsets (int, float4 units) + folded weights,
//      branch-free (out-of-range -> clamp index, zero weight).
//   B: 16 unconditional LDG.128 + FMA, fully unrolled -> ptxas front-batches
//      the loads for high MLP.

#define BS  8
#define NQ  900
#define NH  8
#define DC  32
#define NL  4
#define NPT 4
#define NKEYS 22223
#define KS4 (NH * DC / 4)   // float4s per key = 64

__global__ __launch_bounds__(256, 4) void msda_kernel(
    const float* __restrict__ value,
    const float* __restrict__ loc,
    const float* __restrict__ aw,
    float* __restrict__ out)
{
    const int Hs[NL]     = {100, 50, 25, 13};
    const int Ws[NL]     = {167, 84, 42, 21};
    const int starts[NL] = {0, 16700, 20900, 21950};

    const int gtid = blockIdx.x * blockDim.x + threadIdx.x;
    const int warp = gtid >> 5;          // (b*NQ+q)*NH + h
    const int lane = gtid & 31;
    if (warp >= BS * NQ * NH) return;

    const int g  = lane >> 3;            // point within level (0..3)
    const int cp = lane & 7;             // channel quad (0..7)

    const int h  = warp & (NH - 1);
    const int b  = (warp >> 3) / NQ;

    const float4* __restrict__ v4 =
        (const float4*)value + ((size_t)(b * NKEYS) * NH + h) * (DC / 4) + cp;
    const float2* __restrict__ loc2 = (const float2*)loc;

    // ---------------- Phase A: tap descriptors ----------------
    int   o00[NL], o10[NL], o01[NL], o11[NL];
    float w00[NL], w10[NL], w01[NL], w11[NL];

    #pragma unroll
    for (int lvl = 0; lvl < NL; ++lvl) {
        const int H = Hs[lvl];
        const int W = Ws[lvl];
        const int start = starts[lvl];

        const int li = (warp * NL + lvl) * NPT + g;
        const float2 l2 = __ldg(loc2 + li);
        const float w   = __ldg(aw + li);

        const float x = l2.x * (float)W - 0.5f;
        const float y = l2.y * (float)H - 0.5f;
        const float xf = floorf(x);
        const float yf = floorf(y);
        const int x0 = (int)xf;
        const int y0 = (int)yf;
        const int x1 = x0 + 1;
        const int y1 = y0 + 1;

        float wx1 = x - xf;
        float wx0 = 1.0f - wx1;
        float wy1 = y - yf;
        float wy0 = 1.0f - wy1;

        // clamp index + zero weight for out-of-range taps (branch-free)
        if (x0 < 0 || x0 > W - 1) wx0 = 0.0f;
        if (x1 < 0 || x1 > W - 1) wx1 = 0.0f;
        if (y0 < 0 || y0 > H - 1) wy0 = 0.0f;
        if (y1 < 0 || y1 > H - 1) wy1 = 0.0f;
        const int x0c = min(max(x0, 0), W - 1);
        const int x1c = min(max(x1, 0), W - 1);
        const int y0c = min(max(y0, 0), H - 1);
        const int y1c = min(max(y1, 0), H - 1);

        w00[lvl] = w * wx0 * wy0;
        w10[lvl] = w * wx1 * wy0;
        w01[lvl] = w * wx0 * wy1;
        w11[lvl] = w * wx1 * wy1;

        const int r0 = start + y0c * W;
        const int r1 = start + y1c * W;
        o00[lvl] = (r0 + x0c) * KS4;
        o10[lvl] = (r0 + x1c) * KS4;
        o01[lvl] = (r1 + x0c) * KS4;
        o11[lvl] = (r1 + x1c) * KS4;
    }

    // ---------------- Phase B: gather + accumulate ----------------
    float4 acc = make_float4(0.f, 0.f, 0.f, 0.f);

    #pragma unroll
    for (int lvl = 0; lvl < NL; ++lvl) {
        const float4 a = __ldg(v4 + o00[lvl]);
        const float4 c = __ldg(v4 + o10[lvl]);
        const float4 d = __ldg(v4 + o01[lvl]);
        const float4 e = __ldg(v4 + o11[lvl]);
        const float wa = w00[lvl], wc = w10[lvl], wd = w01[lvl], we = w11[lvl];

        acc.x += a.x * wa + c.x * wc + d.x * wd + e.x * we;
        acc.y += a.y * wa + c.y * wc + d.y * wd + e.y * we;
        acc.z += a.z * wa + c.z * wc + d.z * wd + e.z * we;
        acc.w += a.w * wa + c.w * wc + d.w * wd + e.w * we;
    }

    // reduce the 4 point-groups (lanes cp, cp+8, cp+16, cp+24)
    #pragma unroll
    for (int m = 8; m <= 16; m <<= 1) {
        acc.x += __shfl_xor_sync(0xffffffffu, acc.x, m);
        acc.y += __shfl_xor_sync(0xffffffffu, acc.y, m);
        acc.z += __shfl_xor_sync(0xffffffffu, acc.z, m);
        acc.w += __shfl_xor_sync(0xffffffffu, acc.w, m);
    }

    if (g == 0) {
        ((float4*)out)[(size_t)warp * (DC / 4) + cp] = acc;
    }
}

extern "C" void kernel_launch(void* const* d_in, const int* in_sizes, int n_in,
                              void* d_out, int out_size)
{
    const float* value = (const float*)d_in[0];
    const float* loc   = (const float*)d_in[1];
    const float* aw    = (const float*)d_in[2];
    float* out         = (float*)d_out;

    const int nwarps  = BS * NQ * NH;                     // 57600
    const int threads = 256;
    const int blocks  = (nwarps * 32 + threads - 1) / threads;  // 7200
    msda_kernel<<<blocks, threads>>>(value, loc, aw, out);
}